// round 8
// baseline (speedup 1.0000x reference)
#include <cuda_runtime.h>
#include <math.h>

#define NN 200000
#define NUM_BAGS 25000
#define DD 690
#define D2 345          // DD/2 float2s
#define RR 53

__device__ float g_att[(size_t)NUM_BAGS * DD];  // 69 MB scratch

__device__ __forceinline__ int sniff_is64(const void* scope)
{
    // scope row0 = (start0=0, end0>=1). int32 layout: w[1]=end0>=1 ; int64: w[1]=0
    return (((const int*)scope)[1] == 0) ? 1 : 0;
}

__device__ __forceinline__ int load_idx(const void* p, int i, int is64)
{
    return is64 ? (int)((const long long*)p)[i] : ((const int*)p)[i];
}

// ---------------------------------------------------------------------------
// K1: block per bag, 128 threads. SINGLE pass over repre:
//  each warp runs online softmax over its rows (j = wid + 4k), keeping
//  (m, s, acc[345-f2-sliced]) in registers; 4 partials combined via smem.
// ---------------------------------------------------------------------------
__global__ __launch_bounds__(128) void bag_attn_kernel(
    const float* __restrict__ repre,
    const float* __restrict__ rel,
    const void*  __restrict__ scope,
    const void*  __restrict__ labels)
{
    __shared__ float2 s_acc[4][D2];
    __shared__ float  s_m[4];
    __shared__ float  s_s[4];

    const int tid  = threadIdx.x;
    const int wid  = tid >> 5;     // 0..3
    const int lane = tid & 31;
    const int is64 = sniff_is64(scope);

    const int b = blockIdx.x;
    int start = load_idx(scope, 2 * b, is64);
    int end   = load_idx(scope, 2 * b + 1, is64);
    if (start < 0) start = 0;
    if (start > NN) start = NN;
    if (end < start) end = start;
    if (end > NN) end = NN;
    const int nb = end - start;

    // label prefetch: this warp's k-th row is j = wid + 4k; lane k preloads it
    int mylab = 0;
    {
        const int j = wid + 4 * lane;
        if (j < nb) {
            int lab = load_idx(labels, start + j, is64);
            if (lab < 0) lab = 0;
            if (lab >= RR) lab = RR - 1;
            mylab = lab;
        }
    }

    const bool tailok = (lane < (D2 - 320));   // lane < 25 owns slot it==10

    float2 acc[11];
    #pragma unroll
    for (int it = 0; it < 11; it++) acc[it] = make_float2(0.0f, 0.0f);
    float m = -INFINITY;
    float s = 0.0f;

    for (int k = 0; ; k++) {
        const int j = wid + 4 * k;
        if (j >= nb) break;
        int lab;
        if (k < 32) {
            lab = __shfl_sync(0xffffffffu, mylab, k);
        } else {   // nb > 128: essentially never
            lab = load_idx(labels, start + j, is64);
            if (lab < 0) lab = 0;
            if (lab >= RR) lab = RR - 1;
        }
        const float2* __restrict__ xr2 = (const float2*)(repre + (size_t)(start + j) * DD);
        const float2* __restrict__ rr2 = (const float2*)(rel + (size_t)lab * DD);

        // batch the streaming row loads (deep MLP), rel rows are cache-hot
        float2 x[11];
        #pragma unroll
        for (int it = 0; it < 10; it++) x[it] = __ldcs(&xr2[lane + 32 * it]);
        x[10] = tailok ? __ldcs(&xr2[320 + lane]) : make_float2(0.0f, 0.0f);

        float t = 0.0f;
        #pragma unroll
        for (int it = 0; it < 10; it++) {
            const float2 r = rr2[lane + 32 * it];
            t = fmaf(x[it].x, r.x, t);
            t = fmaf(x[it].y, r.y, t);
        }
        if (tailok) {
            const float2 r = rr2[320 + lane];
            t = fmaf(x[10].x, r.x, t);
            t = fmaf(x[10].y, r.y, t);
        }
        #pragma unroll
        for (int o = 16; o > 0; o >>= 1)
            t += __shfl_xor_sync(0xffffffffu, t, o);

        const float newm = fmaxf(m, t);
        if (newm != m) {
            const float alpha = __expf(m - newm);   // 0 on first row
            s *= alpha;
            #pragma unroll
            for (int it = 0; it < 11; it++) {
                acc[it].x *= alpha;
                acc[it].y *= alpha;
            }
            m = newm;
        }
        const float e = __expf(t - m);
        s += e;
        #pragma unroll
        for (int it = 0; it < 11; it++) {
            acc[it].x = fmaf(e, x[it].x, acc[it].x);
            acc[it].y = fmaf(e, x[it].y, acc[it].y);
        }
    }

    // publish per-warp partials
    if (lane == 0) { s_m[wid] = m; s_s[wid] = s; }
    #pragma unroll
    for (int it = 0; it < 10; it++) s_acc[wid][lane + 32 * it] = acc[it];
    if (tailok) s_acc[wid][320 + lane] = acc[10];
    __syncthreads();

    // combine 4 warp partials (all 128 threads)
    const float m0 = s_m[0], m1 = s_m[1], m2 = s_m[2], m3 = s_m[3];
    const float M  = fmaxf(fmaxf(m0, m1), fmaxf(m2, m3));
    const float a0 = __expf(m0 - M), a1 = __expf(m1 - M);
    const float a2 = __expf(m2 - M), a3 = __expf(m3 - M);
    const float S  = a0 * s_s[0] + a1 * s_s[1] + a2 * s_s[2] + a3 * s_s[3];
    const float inv = 1.0f / S;

    float2* __restrict__ outp = (float2*)(g_att + (size_t)b * DD);
    #pragma unroll
    for (int sl = 0; sl < 3; sl++) {
        const int f = tid + 128 * sl;
        if (f < D2) {
            const float2 v0 = s_acc[0][f], v1 = s_acc[1][f];
            const float2 v2 = s_acc[2][f], v3 = s_acc[3][f];
            float2 v;
            v.x = inv * (a0 * v0.x + a1 * v1.x + a2 * v2.x + a3 * v3.x);
            v.y = inv * (a0 * v0.y + a1 * v1.y + a2 * v2.y + a3 * v3.y);
            outp[f] = v;
        }
    }
}

// ---------------------------------------------------------------------------
// K2: logits = g_att @ rel^T + bias.  BM=64,BN=64,BK=32, 128 threads.
// Microtile (4+4)m x 4n; A operands PRE-PACKED for fma.rn.f32x2 via
// ulonglong2 reinterpretation of LDS.128; B: 1 LDS.128 + 4 dup-packs.
// Global loads are float2 (rows start at 8B alignment only: K=690 ≡ 2 mod 4).
// ---------------------------------------------------------------------------
#define KTILES 22   // ceil(690/32); last tile partial (672..689 valid)

#define FFMA2(acc, a, bb) \
    asm("fma.rn.f32x2 %0, %1, %2, %0;" : "+l"(acc) : "l"(a), "l"(bb))
#define PACK2(out, lo, hi) \
    asm("mov.b64 %0, {%1, %2};" : "=l"(out) : "f"(lo), "f"(hi))
#define UNPACK2(lo, hi, in) \
    asm("mov.b64 {%0, %1}, %2;" : "=f"(lo), "=f"(hi) : "l"(in))

__global__ __launch_bounds__(128) void proj_gemm_kernel(
    const float* __restrict__ relp,
    const float* __restrict__ bias,
    float* __restrict__ out)
{
    const int M = NUM_BAGS;
    const int K = DD;

    __shared__ __align__(16) float As[2][32][68];  // [buf][k][m], row 272B
    __shared__ __align__(16) float Bs[2][32][68];  // [buf][k][n]

    const int tid  = threadIdx.x;
    const int m0   = blockIdx.x * 64;
    const int tm4  = (tid & 7) << 2;    // 0..28  (m group; +32 for upper half)
    const int tn4  = (tid >> 3) << 2;   // 0..60  (n group)

    // tile-load coords: 8 threads per row, 16 rows per pass, 4 passes
    const int lrow = tid >> 3;          // 0..15
    const int lkk  = (tid & 7) << 2;    // 0,4,...,28

    unsigned long long acc2[4][4];      // [mp][n]
    #pragma unroll
    for (int i = 0; i < 4; i++)
        #pragma unroll
        for (int j = 0; j < 4; j++) acc2[i][j] = 0ull;

    float2 vaL[4], vaH[4], vbL[4], vbH[4];

    auto load_tile = [&](int kb) {
        const int k = kb + lkk;
        const bool okL = (k + 1 < K);   // float2 pair [k, k+1]
        const bool okH = (k + 3 < K);   // float2 pair [k+2, k+3]
        #pragma unroll
        for (int p = 0; p < 4; p++) {
            const int row  = lrow + 16 * p;     // 0..63
            const int mrow = m0 + row;
            vaL[p] = make_float2(0.0f, 0.0f);
            vaH[p] = make_float2(0.0f, 0.0f);
            if (mrow < M) {
                const float* base = g_att + (size_t)mrow * K + k;
                if (okL) vaL[p] = __ldcs((const float2*)base);
                if (okH) vaH[p] = __ldcs((const float2*)(base + 2));
            }
            vbL[p] = make_float2(0.0f, 0.0f);
            vbH[p] = make_float2(0.0f, 0.0f);
            if (row < RR) {
                const float* base = relp + (size_t)row * K + k;
                if (okL) vbL[p] = *(const float2*)base;
                if (okH) vbH[p] = *(const float2*)(base + 2);
            }
        }
    };
    auto store_tile = [&](int bufn) {
        #pragma unroll
        for (int p = 0; p < 4; p++) {
            const int row = lrow + 16 * p;
            As[bufn][lkk    ][row] = vaL[p].x;
            As[bufn][lkk + 1][row] = vaL[p].y;
            As[bufn][lkk + 2][row] = vaH[p].x;
            As[bufn][lkk + 3][row] = vaH[p].y;
            Bs[bufn][lkk    ][row] = vbL[p].x;
            Bs[bufn][lkk + 1][row] = vbL[p].y;
            Bs[bufn][lkk + 2][row] = vbH[p].x;
            Bs[bufn][lkk + 3][row] = vbH[p].y;
        }
    };

    load_tile(0);
    store_tile(0);
    __syncthreads();

    int buf = 0;
    for (int kt = 0; kt < KTILES; kt++) {
        const bool more = (kt + 1 < KTILES);
        if (more) load_tile((kt + 1) * 32);

        #pragma unroll
        for (int k = 0; k < 32; k++) {
            const ulonglong2 A0 = *(const ulonglong2*)&As[buf][k][tm4];
            const ulonglong2 A1 = *(const ulonglong2*)&As[buf][k][tm4 + 32];
            const float4 bv     = *(const float4*)&Bs[buf][k][tn4];
            unsigned long long pb0, pb1, pb2, pb3;
            PACK2(pb0, bv.x, bv.x);
            PACK2(pb1, bv.y, bv.y);
            PACK2(pb2, bv.z, bv.z);
            PACK2(pb3, bv.w, bv.w);
            FFMA2(acc2[0][0], A0.x, pb0); FFMA2(acc2[1][0], A0.y, pb0);
            FFMA2(acc2[2][0], A1.x, pb0); FFMA2(acc2[3][0], A1.y, pb0);
            FFMA2(acc2[0][1], A0.x, pb1); FFMA2(acc2[1][1], A0.y, pb1);
            FFMA2(acc2[2][1], A1.x, pb1); FFMA2(acc2[3][1], A1.y, pb1);
            FFMA2(acc2[0][2], A0.x, pb2); FFMA2(acc2[1][2], A0.y, pb2);
            FFMA2(acc2[2][2], A1.x, pb2); FFMA2(acc2[3][2], A1.y, pb2);
            FFMA2(acc2[0][3], A0.x, pb3); FFMA2(acc2[1][3], A0.y, pb3);
            FFMA2(acc2[2][3], A1.x, pb3); FFMA2(acc2[3][3], A1.y, pb3);
        }

        if (more) store_tile(buf ^ 1);
        __syncthreads();
        buf ^= 1;
    }

    #pragma unroll
    for (int np = 0; np < 4; np++) {
        const int n = tn4 + np;
        if (n >= RR) continue;
        const float bval = bias[n];
        #pragma unroll
        for (int mp = 0; mp < 4; mp++) {
            float lo, hi;
            UNPACK2(lo, hi, acc2[mp][np]);
            // acc2[mp]: mp 0,1 -> lower half rows tm4+2*mp{,+1}; mp 2,3 -> +32
            const int mbase = m0 + tm4 + ((mp & 1) << 1) + ((mp >> 1) << 5);
            if (mbase < M)     out[(size_t)mbase * RR + n]       = lo + bval;
            if (mbase + 1 < M) out[(size_t)(mbase + 1) * RR + n] = hi + bval;
        }
    }
}

extern "C" void kernel_launch(void* const* d_in, const int* in_sizes, int n_in,
                              void* d_out, int out_size)
{
    const float* repre  = (const float*)d_in[0];
    const float* relmat = (const float*)d_in[1];
    const float* bias   = (const float*)d_in[2];
    const void*  scope  = d_in[3];
    const void*  labels = d_in[4];
    float* out = (float*)d_out;

    bag_attn_kernel<<<NUM_BAGS, 128>>>(repre, relmat, scope, labels);
    proj_gemm_kernel<<<(NUM_BAGS + 63) / 64, 128>>>(relmat, bias, out);
}

// round 9
// speedup vs baseline: 1.0014x; 1.0014x over previous
#include <cuda_runtime.h>
#include <math.h>

#define NN 200000
#define NUM_BAGS 25000
#define DD 690
#define D2 345          // DD/2 float2s
#define RR 53
#define MAX_BAG 256

__device__ float g_att[(size_t)NUM_BAGS * DD];  // 69 MB scratch

__device__ __forceinline__ int sniff_is64(const void* scope)
{
    // scope row0 = (start0=0, end0>=1). int32 layout: w[1]=end0>=1 ; int64: w[1]=0
    return (((const int*)scope)[1] == 0) ? 1 : 0;
}

__device__ __forceinline__ int load_idx(const void* p, int i, int is64)
{
    return is64 ? (int)((const long long*)p)[i] : ((const int*)p)[i];
}

// ---------------------------------------------------------------------------
// K1 (R6 structure, proven 135us): block per bag, 128 threads.
//  - labels prefetched per warp via registers + SHFL
//  - phase1: warp-per-instance dot (float2, dual accumulators)
//  - softmax: fast path (nb<=32) per-warp redundant, no 2nd barrier
//  - phase3: weighted row sum, 3 slots/thread, unroll x4, __ldcs loads
// ---------------------------------------------------------------------------
__global__ __launch_bounds__(128, 10) void bag_attn_kernel(
    const float* __restrict__ repre,
    const float* __restrict__ rel,
    const void*  __restrict__ scope,
    const void*  __restrict__ labels)
{
    __shared__ float s_rl[MAX_BAG];
    __shared__ float s_w[MAX_BAG];

    const int tid  = threadIdx.x;
    const int wid  = tid >> 5;     // 0..3
    const int lane = tid & 31;
    const int is64 = sniff_is64(scope);

    const int b = blockIdx.x;
    int start = load_idx(scope, 2 * b, is64);
    int end   = load_idx(scope, 2 * b + 1, is64);
    if (start < 0) start = 0;
    if (start > NN) start = NN;
    if (end < start) end = start;
    if (end > NN) end = NN;
    int nb = end - start;
    if (nb > MAX_BAG) nb = MAX_BAG;

    // per-warp label prefetch: warp's k-th row is j = wid + 4k; lane k preloads it
    int mylab = 0;
    {
        const int j = wid + 4 * lane;
        if (j < nb) {
            int lab = load_idx(labels, start + j, is64);
            if (lab < 0) lab = 0;
            if (lab >= RR) lab = RR - 1;
            mylab = lab;
        }
    }

    // ---- phase 1: per-instance logits (warp per instance, float2) ----
    for (int k = 0; ; k++) {
        const int j = wid + 4 * k;
        if (j >= nb) break;
        int lab;
        if (k < 32) {
            lab = __shfl_sync(0xffffffffu, mylab, k);
        } else {
            lab = load_idx(labels, start + j, is64);
            if (lab < 0) lab = 0;
            if (lab >= RR) lab = RR - 1;
        }
        const float2* __restrict__ xr2 = (const float2*)(repre + (size_t)(start + j) * DD);
        const float2* __restrict__ rr2 = (const float2*)(rel + (size_t)lab * DD);
        float accA = 0.0f, accB = 0.0f;
        #pragma unroll
        for (int it = 0; it < 10; it += 2) {
            const int dA = lane + 32 * it;
            const int dB = lane + 32 * (it + 1);
            const float2 xA = xr2[dA];
            const float2 rA = rr2[dA];
            const float2 xB = xr2[dB];
            const float2 rB = rr2[dB];
            accA = fmaf(xA.x, rA.x, accA);
            accA = fmaf(xA.y, rA.y, accA);
            accB = fmaf(xB.x, rB.x, accB);
            accB = fmaf(xB.y, rB.y, accB);
        }
        {
            const int d = 320 + lane;
            if (d < D2) {
                const float2 x = xr2[d];
                const float2 r = rr2[d];
                accA = fmaf(x.x, r.x, accA);
                accA = fmaf(x.y, r.y, accA);
            }
        }
        float acc = accA + accB;
        #pragma unroll
        for (int o = 16; o > 0; o >>= 1)
            acc += __shfl_xor_sync(0xffffffffu, acc, o);
        if (lane == 0) s_rl[j] = acc;
    }
    __syncthreads();

    // ---- phase 2: softmax ----
    const bool fast = (nb <= 32);
    float wreg = 0.0f;
    if (fast) {
        float t = (lane < nb) ? s_rl[lane] : -INFINITY;
        float m = t;
        #pragma unroll
        for (int o = 16; o > 0; o >>= 1)
            m = fmaxf(m, __shfl_xor_sync(0xffffffffu, m, o));
        float e = (lane < nb) ? expf(t - m) : 0.0f;
        float s = e;
        #pragma unroll
        for (int o = 16; o > 0; o >>= 1)
            s += __shfl_xor_sync(0xffffffffu, s, o);
        wreg = e / s;
    } else {
        if (wid == 0) {
            float m = -INFINITY;
            for (int j = lane; j < nb; j += 32) m = fmaxf(m, s_rl[j]);
            #pragma unroll
            for (int o = 16; o > 0; o >>= 1)
                m = fmaxf(m, __shfl_xor_sync(0xffffffffu, m, o));
            float s = 0.0f;
            for (int j = lane; j < nb; j += 32) {
                float e = expf(s_rl[j] - m);
                s_w[j] = e;
                s += e;
            }
            #pragma unroll
            for (int o = 16; o > 0; o >>= 1)
                s += __shfl_xor_sync(0xffffffffu, s, o);
            float inv = 1.0f / s;
            for (int j = lane; j < nb; j += 32) s_w[j] *= inv;
        }
        __syncthreads();
    }

    // ---- phase 3: weighted bag sum (3 slots/thread, unroll x4, streaming) ----
    const int f0 = tid;
    const int f1 = tid + 128;
    const int f2 = tid + 256;
    const bool has2 = (f2 < D2);
    float2 a0 = make_float2(0.0f, 0.0f);
    float2 a1 = make_float2(0.0f, 0.0f);
    float2 a2 = make_float2(0.0f, 0.0f);

    int j = 0;
    for (; j + 3 < nb; j += 4) {
        const float2* __restrict__ x0 = (const float2*)(repre + (size_t)(start + j    ) * DD);
        const float2* __restrict__ x1 = (const float2*)(repre + (size_t)(start + j + 1) * DD);
        const float2* __restrict__ x2 = (const float2*)(repre + (size_t)(start + j + 2) * DD);
        const float2* __restrict__ x3 = (const float2*)(repre + (size_t)(start + j + 3) * DD);
        float w0, w1, w2, w3;
        if (fast) {
            w0 = __shfl_sync(0xffffffffu, wreg, j & 31);
            w1 = __shfl_sync(0xffffffffu, wreg, (j + 1) & 31);
            w2 = __shfl_sync(0xffffffffu, wreg, (j + 2) & 31);
            w3 = __shfl_sync(0xffffffffu, wreg, (j + 3) & 31);
        } else {
            w0 = s_w[j]; w1 = s_w[j + 1]; w2 = s_w[j + 2]; w3 = s_w[j + 3];
        }
        const float2 p00 = __ldcs(&x0[f0]), p10 = __ldcs(&x1[f0]),
                     p20 = __ldcs(&x2[f0]), p30 = __ldcs(&x3[f0]);
        const float2 p01 = __ldcs(&x0[f1]), p11 = __ldcs(&x1[f1]),
                     p21 = __ldcs(&x2[f1]), p31 = __ldcs(&x3[f1]);
        float2 p02, p12, p22, p32;
        if (has2) { p02 = __ldcs(&x0[f2]); p12 = __ldcs(&x1[f2]);
                    p22 = __ldcs(&x2[f2]); p32 = __ldcs(&x3[f2]); }
        a0.x = fmaf(w0, p00.x, a0.x); a0.y = fmaf(w0, p00.y, a0.y);
        a0.x = fmaf(w1, p10.x, a0.x); a0.y = fmaf(w1, p10.y, a0.y);
        a0.x = fmaf(w2, p20.x, a0.x); a0.y = fmaf(w2, p20.y, a0.y);
        a0.x = fmaf(w3, p30.x, a0.x); a0.y = fmaf(w3, p30.y, a0.y);
        a1.x = fmaf(w0, p01.x, a1.x); a1.y = fmaf(w0, p01.y, a1.y);
        a1.x = fmaf(w1, p11.x, a1.x); a1.y = fmaf(w1, p11.y, a1.y);
        a1.x = fmaf(w2, p21.x, a1.x); a1.y = fmaf(w2, p21.y, a1.y);
        a1.x = fmaf(w3, p31.x, a1.x); a1.y = fmaf(w3, p31.y, a1.y);
        if (has2) {
            a2.x = fmaf(w0, p02.x, a2.x); a2.y = fmaf(w0, p02.y, a2.y);
            a2.x = fmaf(w1, p12.x, a2.x); a2.y = fmaf(w1, p12.y, a2.y);
            a2.x = fmaf(w2, p22.x, a2.x); a2.y = fmaf(w2, p22.y, a2.y);
            a2.x = fmaf(w3, p32.x, a2.x); a2.y = fmaf(w3, p32.y, a2.y);
        }
    }
    for (; j < nb; j++) {
        const float2* __restrict__ xA = (const float2*)(repre + (size_t)(start + j) * DD);
        const float wA = fast ? __shfl_sync(0xffffffffu, wreg, j & 31) : s_w[j];
        const float2 v0 = __ldcs(&xA[f0]);
        const float2 v1 = __ldcs(&xA[f1]);
        a0.x = fmaf(wA, v0.x, a0.x); a0.y = fmaf(wA, v0.y, a0.y);
        a1.x = fmaf(wA, v1.x, a1.x); a1.y = fmaf(wA, v1.y, a1.y);
        if (has2) {
            const float2 v2 = __ldcs(&xA[f2]);
            a2.x = fmaf(wA, v2.x, a2.x); a2.y = fmaf(wA, v2.y, a2.y);
        }
    }

    float2* __restrict__ outp = (float2*)(g_att + (size_t)b * DD);
    outp[f0] = a0;
    outp[f1] = a1;
    if (has2) outp[f2] = a2;
}

// ---------------------------------------------------------------------------
// K2: logits = g_att @ rel^T + bias.  BM=128, BN=64, BK=32, 128 threads.
// Per-thread microtile (8+8)m x (4+4)n with f32x2 packed accumulation.
// Per warp-k: 4 LDS.128 for 64 FMAs/thread -> L1-wavefront and FFMA2 pipe
// both ~45k cyc/SM.  Global loads float2 (rows are 8B-aligned only).
// ---------------------------------------------------------------------------
#define KTILES 22   // ceil(690/32); last tile partial (672..689 valid)

#define FFMA2(acc, a, bb) \
    asm("fma.rn.f32x2 %0, %1, %2, %0;" : "+l"(acc) : "l"(a), "l"(bb))
#define PACK2(out, lo, hi) \
    asm("mov.b64 %0, {%1, %2};" : "=l"(out) : "f"(lo), "f"(hi))
#define UNPACK2(lo, hi, in) \
    asm("mov.b64 {%0, %1}, %2;" : "=f"(lo), "=f"(hi) : "l"(in))

__global__ __launch_bounds__(128) void proj_gemm_kernel(
    const float* __restrict__ relp,
    const float* __restrict__ bias,
    float* __restrict__ out)
{
    const int M = NUM_BAGS;
    const int K = DD;

    __shared__ __align__(16) float As[2][32][128];  // [buf][k][m] 16KB each
    __shared__ __align__(16) float Bs[2][32][64];   // [buf][k][n]  8KB each

    const int tid = threadIdx.x;
    const int m0  = blockIdx.x * 128;
    const int tmq = (tid & 15) << 2;    // m base (second half +64)
    const int tnq = (tid >> 4) << 2;    // n base (second half +32)

    // tile staging coords
    const int arow  = tid;              // A: one row per thread, 16 f2 along k
    const int bn    = tid & 63;         // B: n row
    const int bkoff = (tid >> 6) << 4;  // B: k offset 0 or 16 (8 f2 each)

    unsigned long long acc[2][2][8];    // [mhalf][mpair][n8]
    #pragma unroll
    for (int h = 0; h < 2; h++)
        #pragma unroll
        for (int p = 0; p < 2; p++)
            #pragma unroll
            for (int q = 0; q < 8; q++) acc[h][p][q] = 0ull;

    float2 va[16], vb[8];

    auto load_tile = [&](int kb) {
        const bool arowok = (m0 + arow < M);
        const float* abase = g_att + (size_t)(m0 + arow) * K + kb;
        #pragma unroll
        for (int i = 0; i < 16; i++) {
            va[i] = make_float2(0.0f, 0.0f);
            if (arowok && kb + 2 * i + 1 < K)
                va[i] = __ldcs((const float2*)(abase + 2 * i));
        }
        const bool bok = (bn < RR);
        const float* bbase = relp + (size_t)bn * K + kb + bkoff;
        #pragma unroll
        for (int i = 0; i < 8; i++) {
            vb[i] = make_float2(0.0f, 0.0f);
            if (bok && kb + bkoff + 2 * i + 1 < K)
                vb[i] = *(const float2*)(bbase + 2 * i);
        }
    };
    auto store_tile = [&](int bufn) {
        #pragma unroll
        for (int i = 0; i < 16; i++) {
            As[bufn][2 * i][arow]     = va[i].x;
            As[bufn][2 * i + 1][arow] = va[i].y;
        }
        #pragma unroll
        for (int i = 0; i < 8; i++) {
            Bs[bufn][bkoff + 2 * i][bn]     = vb[i].x;
            Bs[bufn][bkoff + 2 * i + 1][bn] = vb[i].y;
        }
    };

    load_tile(0);
    store_tile(0);
    __syncthreads();

    int buf = 0;
    for (int kt = 0; kt < KTILES; kt++) {
        const bool more = (kt + 1 < KTILES);
        if (more) load_tile((kt + 1) * 32);

        #pragma unroll
        for (int k = 0; k < 32; k++) {
            const ulonglong2 A0 = *(const ulonglong2*)&As[buf][k][tmq];
            const ulonglong2 A1 = *(const ulonglong2*)&As[buf][k][tmq + 64];
            const float4 b0     = *(const float4*)&Bs[buf][k][tnq];
            const float4 b1     = *(const float4*)&Bs[buf][k][tnq + 32];
            unsigned long long p0, p1, p2, p3, p4, p5, p6, p7;
            PACK2(p0, b0.x, b0.x); PACK2(p1, b0.y, b0.y);
            PACK2(p2, b0.z, b0.z); PACK2(p3, b0.w, b0.w);
            PACK2(p4, b1.x, b1.x); PACK2(p5, b1.y, b1.y);
            PACK2(p6, b1.z, b1.z); PACK2(p7, b1.w, b1.w);
            FFMA2(acc[0][0][0], A0.x, p0); FFMA2(acc[0][1][0], A0.y, p0);
            FFMA2(acc[1][0][0], A1.x, p0); FFMA2(acc[1][1][0], A1.y, p0);
            FFMA2(acc[0][0][1], A0.x, p1); FFMA2(acc[0][1][1], A0.y, p1);
            FFMA2(acc[1][0][1], A1.x, p1); FFMA2(acc[1][1][1], A1.y, p1);
            FFMA2(acc[0][0][2], A0.x, p2); FFMA2(acc[0][1][2], A0.y, p2);
            FFMA2(acc[1][0][2], A1.x, p2); FFMA2(acc[1][1][2], A1.y, p2);
            FFMA2(acc[0][0][3], A0.x, p3); FFMA2(acc[0][1][3], A0.y, p3);
            FFMA2(acc[1][0][3], A1.x, p3); FFMA2(acc[1][1][3], A1.y, p3);
            FFMA2(acc[0][0][4], A0.x, p4); FFMA2(acc[0][1][4], A0.y, p4);
            FFMA2(acc[1][0][4], A1.x, p4); FFMA2(acc[1][1][4], A1.y, p4);
            FFMA2(acc[0][0][5], A0.x, p5); FFMA2(acc[0][1][5], A0.y, p5);
            FFMA2(acc[1][0][5], A1.x, p5); FFMA2(acc[1][1][5], A1.y, p5);
            FFMA2(acc[0][0][6], A0.x, p6); FFMA2(acc[0][1][6], A0.y, p6);
            FFMA2(acc[1][0][6], A1.x, p6); FFMA2(acc[1][1][6], A1.y, p6);
            FFMA2(acc[0][0][7], A0.x, p7); FFMA2(acc[0][1][7], A0.y, p7);
            FFMA2(acc[1][0][7], A1.x, p7); FFMA2(acc[1][1][7], A1.y, p7);
        }

        if (more) store_tile(buf ^ 1);
        __syncthreads();
        buf ^= 1;
    }

    #pragma unroll
    for (int q = 0; q < 8; q++) {
        const int n = tnq + ((q < 4) ? q : (28 + q));   // q>=4: +32+(q-4)
        if (n >= RR) continue;
        const float bval = bias[n];
        #pragma unroll
        for (int h = 0; h < 2; h++) {
            #pragma unroll
            for (int p = 0; p < 2; p++) {
                float lo, hi;
                UNPACK2(lo, hi, acc[h][p][q]);
                const int mA = m0 + tmq + 64 * h + 2 * p;
                if (mA < M)     out[(size_t)mA * RR + n]       = lo + bval;
                if (mA + 1 < M) out[(size_t)(mA + 1) * RR + n] = hi + bval;
            }
        }
    }
}

extern "C" void kernel_launch(void* const* d_in, const int* in_sizes, int n_in,
                              void* d_out, int out_size)
{
    const float* repre  = (const float*)d_in[0];
    const float* relmat = (const float*)d_in[1];
    const float* bias   = (const float*)d_in[2];
    const void*  scope  = d_in[3];
    const void*  labels = d_in[4];
    float* out = (float*)d_out;

    bag_attn_kernel<<<NUM_BAGS, 128>>>(repre, relmat, scope, labels);
    proj_gemm_kernel<<<(NUM_BAGS + 127) / 128, 128>>>(relmat, bias, out);
}

// round 10
// speedup vs baseline: 1.0986x; 1.0971x over previous
#include <cuda_runtime.h>
#include <math.h>

#define NN 200000
#define NUM_BAGS 25000
#define DD 690
#define D2 345          // DD/2 float2s
#define RR 53
#define MAX_BAG 256

__device__ float g_att[(size_t)NUM_BAGS * DD];  // 69 MB scratch

__device__ __forceinline__ int sniff_is64(const void* scope)
{
    // scope row0 = (start0=0, end0>=1). int32 layout: w[1]=end0>=1 ; int64: w[1]=0
    return (((const int*)scope)[1] == 0) ? 1 : 0;
}

__device__ __forceinline__ int load_idx(const void* p, int i, int is64)
{
    return is64 ? (int)((const long long*)p)[i] : ((const int*)p)[i];
}

// ---------------------------------------------------------------------------
// K1 (exact R6 structure, measured 135us): block per bag, 128 threads.
// ---------------------------------------------------------------------------
__global__ __launch_bounds__(128, 10) void bag_attn_kernel(
    const float* __restrict__ repre,
    const float* __restrict__ rel,
    const void*  __restrict__ scope,
    const void*  __restrict__ labels)
{
    __shared__ float s_rl[MAX_BAG];
    __shared__ float s_w[MAX_BAG];

    const int tid  = threadIdx.x;
    const int wid  = tid >> 5;     // 0..3
    const int lane = tid & 31;
    const int is64 = sniff_is64(scope);

    const int b = blockIdx.x;
    int start = load_idx(scope, 2 * b, is64);
    int end   = load_idx(scope, 2 * b + 1, is64);
    if (start < 0) start = 0;
    if (start > NN) start = NN;
    if (end < start) end = start;
    if (end > NN) end = NN;
    int nb = end - start;
    if (nb > MAX_BAG) nb = MAX_BAG;

    // per-warp label prefetch: warp's k-th row is j = wid + 4k; lane k preloads it
    int mylab = 0;
    {
        const int j = wid + 4 * lane;
        if (j < nb) {
            int lab = load_idx(labels, start + j, is64);
            if (lab < 0) lab = 0;
            if (lab >= RR) lab = RR - 1;
            mylab = lab;
        }
    }

    // ---- phase 1: per-instance logits (warp per instance, float2) ----
    for (int k = 0; ; k++) {
        const int j = wid + 4 * k;
        if (j >= nb) break;
        int lab;
        if (k < 32) {
            lab = __shfl_sync(0xffffffffu, mylab, k);
        } else {
            lab = load_idx(labels, start + j, is64);
            if (lab < 0) lab = 0;
            if (lab >= RR) lab = RR - 1;
        }
        const float2* __restrict__ xr2 = (const float2*)(repre + (size_t)(start + j) * DD);
        const float2* __restrict__ rr2 = (const float2*)(rel + (size_t)lab * DD);
        float acc = 0.0f;
        #pragma unroll
        for (int it = 0; it < 10; it++) {
            const int d = lane + 32 * it;
            const float2 x = xr2[d];
            const float2 r = rr2[d];
            acc = fmaf(x.x, r.x, acc);
            acc = fmaf(x.y, r.y, acc);
        }
        {
            const int d = 320 + lane;
            if (d < D2) {
                const float2 x = xr2[d];
                const float2 r = rr2[d];
                acc = fmaf(x.x, r.x, acc);
                acc = fmaf(x.y, r.y, acc);
            }
        }
        #pragma unroll
        for (int o = 16; o > 0; o >>= 1)
            acc += __shfl_xor_sync(0xffffffffu, acc, o);
        if (lane == 0) s_rl[j] = acc;
    }
    __syncthreads();

    // ---- phase 2: softmax ----
    const bool fast = (nb <= 32);
    float wreg = 0.0f;
    if (fast) {
        float t = (lane < nb) ? s_rl[lane] : -INFINITY;
        float m = t;
        #pragma unroll
        for (int o = 16; o > 0; o >>= 1)
            m = fmaxf(m, __shfl_xor_sync(0xffffffffu, m, o));
        float e = (lane < nb) ? expf(t - m) : 0.0f;
        float s = e;
        #pragma unroll
        for (int o = 16; o > 0; o >>= 1)
            s += __shfl_xor_sync(0xffffffffu, s, o);
        wreg = e / s;
    } else {
        if (wid == 0) {
            float m = -INFINITY;
            for (int j = lane; j < nb; j += 32) m = fmaxf(m, s_rl[j]);
            #pragma unroll
            for (int o = 16; o > 0; o >>= 1)
                m = fmaxf(m, __shfl_xor_sync(0xffffffffu, m, o));
            float s = 0.0f;
            for (int j = lane; j < nb; j += 32) {
                float e = expf(s_rl[j] - m);
                s_w[j] = e;
                s += e;
            }
            #pragma unroll
            for (int o = 16; o > 0; o >>= 1)
                s += __shfl_xor_sync(0xffffffffu, s, o);
            float inv = 1.0f / s;
            for (int j = lane; j < nb; j += 32) s_w[j] *= inv;
        }
        __syncthreads();
    }

    // ---- phase 3: weighted bag sum (3 slots/thread, unroll x4, streaming) ----
    const int f0 = tid;
    const int f1 = tid + 128;
    const int f2 = tid + 256;
    const bool has2 = (f2 < D2);
    float2 a0 = make_float2(0.0f, 0.0f);
    float2 a1 = make_float2(0.0f, 0.0f);
    float2 a2 = make_float2(0.0f, 0.0f);

    int j = 0;
    for (; j + 3 < nb; j += 4) {
        const float2* __restrict__ x0 = (const float2*)(repre + (size_t)(start + j    ) * DD);
        const float2* __restrict__ x1 = (const float2*)(repre + (size_t)(start + j + 1) * DD);
        const float2* __restrict__ x2 = (const float2*)(repre + (size_t)(start + j + 2) * DD);
        const float2* __restrict__ x3 = (const float2*)(repre + (size_t)(start + j + 3) * DD);
        float w0, w1, w2, w3;
        if (fast) {
            w0 = __shfl_sync(0xffffffffu, wreg, j & 31);
            w1 = __shfl_sync(0xffffffffu, wreg, (j + 1) & 31);
            w2 = __shfl_sync(0xffffffffu, wreg, (j + 2) & 31);
            w3 = __shfl_sync(0xffffffffu, wreg, (j + 3) & 31);
        } else {
            w0 = s_w[j]; w1 = s_w[j + 1]; w2 = s_w[j + 2]; w3 = s_w[j + 3];
        }
        const float2 p00 = __ldcs(&x0[f0]), p10 = __ldcs(&x1[f0]),
                     p20 = __ldcs(&x2[f0]), p30 = __ldcs(&x3[f0]);
        const float2 p01 = __ldcs(&x0[f1]), p11 = __ldcs(&x1[f1]),
                     p21 = __ldcs(&x2[f1]), p31 = __ldcs(&x3[f1]);
        float2 p02, p12, p22, p32;
        if (has2) { p02 = __ldcs(&x0[f2]); p12 = __ldcs(&x1[f2]);
                    p22 = __ldcs(&x2[f2]); p32 = __ldcs(&x3[f2]); }
        a0.x = fmaf(w0, p00.x, a0.x); a0.y = fmaf(w0, p00.y, a0.y);
        a0.x = fmaf(w1, p10.x, a0.x); a0.y = fmaf(w1, p10.y, a0.y);
        a0.x = fmaf(w2, p20.x, a0.x); a0.y = fmaf(w2, p20.y, a0.y);
        a0.x = fmaf(w3, p30.x, a0.x); a0.y = fmaf(w3, p30.y, a0.y);
        a1.x = fmaf(w0, p01.x, a1.x); a1.y = fmaf(w0, p01.y, a1.y);
        a1.x = fmaf(w1, p11.x, a1.x); a1.y = fmaf(w1, p11.y, a1.y);
        a1.x = fmaf(w2, p21.x, a1.x); a1.y = fmaf(w2, p21.y, a1.y);
        a1.x = fmaf(w3, p31.x, a1.x); a1.y = fmaf(w3, p31.y, a1.y);
        if (has2) {
            a2.x = fmaf(w0, p02.x, a2.x); a2.y = fmaf(w0, p02.y, a2.y);
            a2.x = fmaf(w1, p12.x, a2.x); a2.y = fmaf(w1, p12.y, a2.y);
            a2.x = fmaf(w2, p22.x, a2.x); a2.y = fmaf(w2, p22.y, a2.y);
            a2.x = fmaf(w3, p32.x, a2.x); a2.y = fmaf(w3, p32.y, a2.y);
        }
    }
    for (; j < nb; j++) {
        const float2* __restrict__ xA = (const float2*)(repre + (size_t)(start + j) * DD);
        const float wA = fast ? __shfl_sync(0xffffffffu, wreg, j & 31) : s_w[j];
        const float2 v0 = __ldcs(&xA[f0]);
        const float2 v1 = __ldcs(&xA[f1]);
        a0.x = fmaf(wA, v0.x, a0.x); a0.y = fmaf(wA, v0.y, a0.y);
        a1.x = fmaf(wA, v1.x, a1.x); a1.y = fmaf(wA, v1.y, a1.y);
        if (has2) {
            const float2 v2 = __ldcs(&xA[f2]);
            a2.x = fmaf(wA, v2.x, a2.x); a2.y = fmaf(wA, v2.y, a2.y);
        }
    }

    float2* __restrict__ outp = (float2*)(g_att + (size_t)b * DD);
    outp[f0] = a0;
    outp[f1] = a1;
    if (has2) outp[f2] = a2;
}

// ---------------------------------------------------------------------------
// K2 (exact R8 structure, measured 74.4us): BM=64,BN=64,BK=32, 128 threads.
// Microtile (4+4)m x 4n; A operands PRE-PACKED for fma.rn.f32x2 via
// ulonglong2 reinterpretation of LDS.128; B: 1 LDS.128 + 4 dup-packs.
// ---------------------------------------------------------------------------
#define KTILES 22   // ceil(690/32); last tile partial (672..689 valid)

#define FFMA2(acc, a, bb) \
    asm("fma.rn.f32x2 %0, %1, %2, %0;" : "+l"(acc) : "l"(a), "l"(bb))
#define PACK2(out, lo, hi) \
    asm("mov.b64 %0, {%1, %2};" : "=l"(out) : "f"(lo), "f"(hi))
#define UNPACK2(lo, hi, in) \
    asm("mov.b64 {%0, %1}, %2;" : "=f"(lo), "=f"(hi) : "l"(in))

__global__ __launch_bounds__(128) void proj_gemm_kernel(
    const float* __restrict__ relp,
    const float* __restrict__ bias,
    float* __restrict__ out)
{
    const int M = NUM_BAGS;
    const int K = DD;

    __shared__ __align__(16) float As[2][32][68];  // [buf][k][m], row 272B
    __shared__ __align__(16) float Bs[2][32][68];  // [buf][k][n]

    const int tid  = threadIdx.x;
    const int m0   = blockIdx.x * 64;
    const int tm4  = (tid & 7) << 2;    // 0..28  (m group; +32 for upper half)
    const int tn4  = (tid >> 3) << 2;   // 0..60  (n group)

    const int lrow = tid >> 3;          // 0..15
    const int lkk  = (tid & 7) << 2;    // 0,4,...,28

    unsigned long long acc2[4][4];      // [mp][n]
    #pragma unroll
    for (int i = 0; i < 4; i++)
        #pragma unroll
        for (int j = 0; j < 4; j++) acc2[i][j] = 0ull;

    float2 vaL[4], vaH[4], vbL[4], vbH[4];

    auto load_tile = [&](int kb) {
        const int k = kb + lkk;
        const bool okL = (k + 1 < K);
        const bool okH = (k + 3 < K);
        #pragma unroll
        for (int p = 0; p < 4; p++) {
            const int row  = lrow + 16 * p;
            const int mrow = m0 + row;
            vaL[p] = make_float2(0.0f, 0.0f);
            vaH[p] = make_float2(0.0f, 0.0f);
            if (mrow < M) {
                const float* base = g_att + (size_t)mrow * K + k;
                if (okL) vaL[p] = __ldcs((const float2*)base);
                if (okH) vaH[p] = __ldcs((const float2*)(base + 2));
            }
            vbL[p] = make_float2(0.0f, 0.0f);
            vbH[p] = make_float2(0.0f, 0.0f);
            if (row < RR) {
                const float* base = relp + (size_t)row * K + k;
                if (okL) vbL[p] = *(const float2*)base;
                if (okH) vbH[p] = *(const float2*)(base + 2);
            }
        }
    };
    auto store_tile = [&](int bufn) {
        #pragma unroll
        for (int p = 0; p < 4; p++) {
            const int row = lrow + 16 * p;
            As[bufn][lkk    ][row] = vaL[p].x;
            As[bufn][lkk + 1][row] = vaL[p].y;
            As[bufn][lkk + 2][row] = vaH[p].x;
            As[bufn][lkk + 3][row] = vaH[p].y;
            Bs[bufn][lkk    ][row] = vbL[p].x;
            Bs[bufn][lkk + 1][row] = vbL[p].y;
            Bs[bufn][lkk + 2][row] = vbH[p].x;
            Bs[bufn][lkk + 3][row] = vbH[p].y;
        }
    };

    load_tile(0);
    store_tile(0);
    __syncthreads();

    int buf = 0;
    for (int kt = 0; kt < KTILES; kt++) {
        const bool more = (kt + 1 < KTILES);
        if (more) load_tile((kt + 1) * 32);

        #pragma unroll
        for (int k = 0; k < 32; k++) {
            const ulonglong2 A0 = *(const ulonglong2*)&As[buf][k][tm4];
            const ulonglong2 A1 = *(const ulonglong2*)&As[buf][k][tm4 + 32];
            const float4 bv     = *(const float4*)&Bs[buf][k][tn4];
            unsigned long long pb0, pb1, pb2, pb3;
            PACK2(pb0, bv.x, bv.x);
            PACK2(pb1, bv.y, bv.y);
            PACK2(pb2, bv.z, bv.z);
            PACK2(pb3, bv.w, bv.w);
            FFMA2(acc2[0][0], A0.x, pb0); FFMA2(acc2[1][0], A0.y, pb0);
            FFMA2(acc2[2][0], A1.x, pb0); FFMA2(acc2[3][0], A1.y, pb0);
            FFMA2(acc2[0][1], A0.x, pb1); FFMA2(acc2[1][1], A0.y, pb1);
            FFMA2(acc2[2][1], A1.x, pb1); FFMA2(acc2[3][1], A1.y, pb1);
            FFMA2(acc2[0][2], A0.x, pb2); FFMA2(acc2[1][2], A0.y, pb2);
            FFMA2(acc2[2][2], A1.x, pb2); FFMA2(acc2[3][2], A1.y, pb2);
            FFMA2(acc2[0][3], A0.x, pb3); FFMA2(acc2[1][3], A0.y, pb3);
            FFMA2(acc2[2][3], A1.x, pb3); FFMA2(acc2[3][3], A1.y, pb3);
        }

        if (more) store_tile(buf ^ 1);
        __syncthreads();
        buf ^= 1;
    }

    #pragma unroll
    for (int np = 0; np < 4; np++) {
        const int n = tn4 + np;
        if (n >= RR) continue;
        const float bval = bias[n];
        #pragma unroll
        for (int mp = 0; mp < 4; mp++) {
            float lo, hi;
            UNPACK2(lo, hi, acc2[mp][np]);
            const int mbase = m0 + tm4 + ((mp & 1) << 1) + ((mp >> 1) << 5);
            if (mbase < M)     out[(size_t)mbase * RR + n]       = lo + bval;
            if (mbase + 1 < M) out[(size_t)(mbase + 1) * RR + n] = hi + bval;
        }
    }
}

extern "C" void kernel_launch(void* const* d_in, const int* in_sizes, int n_in,
                              void* d_out, int out_size)
{
    const float* repre  = (const float*)d_in[0];
    const float* relmat = (const float*)d_in[1];
    const float* bias   = (const float*)d_in[2];
    const void*  scope  = d_in[3];
    const void*  labels = d_in[4];
    float* out = (float*)d_out;

    bag_attn_kernel<<<NUM_BAGS, 128>>>(repre, relmat, scope, labels);
    proj_gemm_kernel<<<(NUM_BAGS + 63) / 64, 128>>>(relmat, bias, out);
}

// round 12
// speedup vs baseline: 1.1683x; 1.0634x over previous
#include <cuda_runtime.h>
#include <cuda_bf16.h>
#include <math.h>
#include <cstdint>

#define NN 200000
#define NUM_BAGS 25000
#define DD 690
#define D2 345          // DD/2 float2s
#define RR 53
#define MAX_BAG 256
#define KPAD 704        // DD padded to 44*16
#define PAIRS 352       // KPAD/2 bf16x2 pairs per row

// Interleaved (hi,lo) bf16x2 storage: row-major, u32 col 2c = hi pair (d=2c,2c+1),
// u32 col 2c+1 = lo pair. Cols for d>=690 stay zero (static zero-init, never written).
__device__ uint32_t g_att_hl[(size_t)NUM_BAGS * KPAD];   // 70.4 MB
__device__ uint32_t g_rel_hl[(size_t)64 * KPAD];         // 180 KB (n padded to 64)

__device__ __forceinline__ int sniff_is64(const void* scope)
{
    return (((const int*)scope)[1] == 0) ? 1 : 0;
}

__device__ __forceinline__ int load_idx(const void* p, int i, int is64)
{
    return is64 ? (int)((const long long*)p)[i] : ((const int*)p)[i];
}

__device__ __forceinline__ void store_hl(uint32_t* __restrict__ row, int f, float2 v)
{
    __nv_bfloat16 hx = __float2bfloat16(v.x);
    __nv_bfloat16 hy = __float2bfloat16(v.y);
    __nv_bfloat16 lx = __float2bfloat16(v.x - __bfloat162float(hx));
    __nv_bfloat16 ly = __float2bfloat16(v.y - __bfloat162float(hy));
    __nv_bfloat162 hh; hh.x = hx; hh.y = hy;
    __nv_bfloat162 ll; ll.x = lx; ll.y = ly;
    row[2 * f]     = *reinterpret_cast<uint32_t*>(&hh);
    row[2 * f + 1] = *reinterpret_cast<uint32_t*>(&ll);
}

// ---------------------------------------------------------------------------
// rel prep: split relation_mat into (hi,lo) bf16x2 interleaved, n padded to 64.
// ---------------------------------------------------------------------------
__global__ void rel_prep_kernel(const float* __restrict__ relp)
{
    const int n = blockIdx.x;            // 0..63
    uint32_t* dst = g_rel_hl + (size_t)n * KPAD;
    for (int c = threadIdx.x; c < PAIRS; c += blockDim.x) {
        float v0 = 0.0f, v1 = 0.0f;
        if (n < RR) {
            const int d0 = 2 * c;
            if (d0 < DD)     v0 = relp[(size_t)n * DD + d0];
            if (d0 + 1 < DD) v1 = relp[(size_t)n * DD + d0 + 1];
        }
        store_hl(dst, c, make_float2(v0, v1));
    }
}

// ---------------------------------------------------------------------------
// K1 (R10 structure, measured ~137us): block per bag, 128 threads.
// Epilogue now writes (hi,lo) bf16x2 pairs to g_att_hl.
// ---------------------------------------------------------------------------
__global__ __launch_bounds__(128, 10) void bag_attn_kernel(
    const float* __restrict__ repre,
    const float* __restrict__ rel,
    const void*  __restrict__ scope,
    const void*  __restrict__ labels)
{
    __shared__ float s_rl[MAX_BAG];
    __shared__ float s_w[MAX_BAG];

    const int tid  = threadIdx.x;
    const int wid  = tid >> 5;
    const int lane = tid & 31;
    const int is64 = sniff_is64(scope);

    const int b = blockIdx.x;
    int start = load_idx(scope, 2 * b, is64);
    int end   = load_idx(scope, 2 * b + 1, is64);
    if (start < 0) start = 0;
    if (start > NN) start = NN;
    if (end < start) end = start;
    if (end > NN) end = NN;
    int nb = end - start;
    if (nb > MAX_BAG) nb = MAX_BAG;

    int mylab = 0;
    {
        const int j = wid + 4 * lane;
        if (j < nb) {
            int lab = load_idx(labels, start + j, is64);
            if (lab < 0) lab = 0;
            if (lab >= RR) lab = RR - 1;
            mylab = lab;
        }
    }

    for (int k = 0; ; k++) {
        const int j = wid + 4 * k;
        if (j >= nb) break;
        int lab;
        if (k < 32) {
            lab = __shfl_sync(0xffffffffu, mylab, k);
        } else {
            lab = load_idx(labels, start + j, is64);
            if (lab < 0) lab = 0;
            if (lab >= RR) lab = RR - 1;
        }
        const float2* __restrict__ xr2 = (const float2*)(repre + (size_t)(start + j) * DD);
        const float2* __restrict__ rr2 = (const float2*)(rel + (size_t)lab * DD);
        float acc = 0.0f;
        #pragma unroll
        for (int it = 0; it < 10; it++) {
            const int d = lane + 32 * it;
            const float2 x = xr2[d];
            const float2 r = rr2[d];
            acc = fmaf(x.x, r.x, acc);
            acc = fmaf(x.y, r.y, acc);
        }
        {
            const int d = 320 + lane;
            if (d < D2) {
                const float2 x = xr2[d];
                const float2 r = rr2[d];
                acc = fmaf(x.x, r.x, acc);
                acc = fmaf(x.y, r.y, acc);
            }
        }
        #pragma unroll
        for (int o = 16; o > 0; o >>= 1)
            acc += __shfl_xor_sync(0xffffffffu, acc, o);
        if (lane == 0) s_rl[j] = acc;
    }
    __syncthreads();

    const bool fast = (nb <= 32);
    float wreg = 0.0f;
    if (fast) {
        float t = (lane < nb) ? s_rl[lane] : -INFINITY;
        float m = t;
        #pragma unroll
        for (int o = 16; o > 0; o >>= 1)
            m = fmaxf(m, __shfl_xor_sync(0xffffffffu, m, o));
        float e = (lane < nb) ? expf(t - m) : 0.0f;
        float s = e;
        #pragma unroll
        for (int o = 16; o > 0; o >>= 1)
            s += __shfl_xor_sync(0xffffffffu, s, o);
        wreg = e / s;
    } else {
        if (wid == 0) {
            float m = -INFINITY;
            for (int j = lane; j < nb; j += 32) m = fmaxf(m, s_rl[j]);
            #pragma unroll
            for (int o = 16; o > 0; o >>= 1)
                m = fmaxf(m, __shfl_xor_sync(0xffffffffu, m, o));
            float s = 0.0f;
            for (int j = lane; j < nb; j += 32) {
                float e = expf(s_rl[j] - m);
                s_w[j] = e;
                s += e;
            }
            #pragma unroll
            for (int o = 16; o > 0; o >>= 1)
                s += __shfl_xor_sync(0xffffffffu, s, o);
            float inv = 1.0f / s;
            for (int j = lane; j < nb; j += 32) s_w[j] *= inv;
        }
        __syncthreads();
    }

    const int f0 = tid;
    const int f1 = tid + 128;
    const int f2 = tid + 256;
    const bool has2 = (f2 < D2);
    float2 a0 = make_float2(0.0f, 0.0f);
    float2 a1 = make_float2(0.0f, 0.0f);
    float2 a2 = make_float2(0.0f, 0.0f);

    int j = 0;
    for (; j + 3 < nb; j += 4) {
        const float2* __restrict__ x0 = (const float2*)(repre + (size_t)(start + j    ) * DD);
        const float2* __restrict__ x1 = (const float2*)(repre + (size_t)(start + j + 1) * DD);
        const float2* __restrict__ x2 = (const float2*)(repre + (size_t)(start + j + 2) * DD);
        const float2* __restrict__ x3 = (const float2*)(repre + (size_t)(start + j + 3) * DD);
        float w0, w1, w2, w3;
        if (fast) {
            w0 = __shfl_sync(0xffffffffu, wreg, j & 31);
            w1 = __shfl_sync(0xffffffffu, wreg, (j + 1) & 31);
            w2 = __shfl_sync(0xffffffffu, wreg, (j + 2) & 31);
            w3 = __shfl_sync(0xffffffffu, wreg, (j + 3) & 31);
        } else {
            w0 = s_w[j]; w1 = s_w[j + 1]; w2 = s_w[j + 2]; w3 = s_w[j + 3];
        }
        const float2 p00 = __ldcs(&x0[f0]), p10 = __ldcs(&x1[f0]),
                     p20 = __ldcs(&x2[f0]), p30 = __ldcs(&x3[f0]);
        const float2 p01 = __ldcs(&x0[f1]), p11 = __ldcs(&x1[f1]),
                     p21 = __ldcs(&x2[f1]), p31 = __ldcs(&x3[f1]);
        float2 p02, p12, p22, p32;
        if (has2) { p02 = __ldcs(&x0[f2]); p12 = __ldcs(&x1[f2]);
                    p22 = __ldcs(&x2[f2]); p32 = __ldcs(&x3[f2]); }
        a0.x = fmaf(w0, p00.x, a0.x); a0.y = fmaf(w0, p00.y, a0.y);
        a0.x = fmaf(w1, p10.x, a0.x); a0.y = fmaf(w1, p10.y, a0.y);
        a0.x = fmaf(w2, p20.x, a0.x); a0.y = fmaf(w2, p20.y, a0.y);
        a0.x = fmaf(w3, p30.x, a0.x); a0.y = fmaf(w3, p30.y, a0.y);
        a1.x = fmaf(w0, p01.x, a1.x); a1.y = fmaf(w0, p01.y, a1.y);
        a1.x = fmaf(w1, p11.x, a1.x); a1.y = fmaf(w1, p11.y, a1.y);
        a1.x = fmaf(w2, p21.x, a1.x); a1.y = fmaf(w2, p21.y, a1.y);
        a1.x = fmaf(w3, p31.x, a1.x); a1.y = fmaf(w3, p31.y, a1.y);
        if (has2) {
            a2.x = fmaf(w0, p02.x, a2.x); a2.y = fmaf(w0, p02.y, a2.y);
            a2.x = fmaf(w1, p12.x, a2.x); a2.y = fmaf(w1, p12.y, a2.y);
            a2.x = fmaf(w2, p22.x, a2.x); a2.y = fmaf(w2, p22.y, a2.y);
            a2.x = fmaf(w3, p32.x, a2.x); a2.y = fmaf(w3, p32.y, a2.y);
        }
    }
    for (; j < nb; j++) {
        const float2* __restrict__ xA = (const float2*)(repre + (size_t)(start + j) * DD);
        const float wA = fast ? __shfl_sync(0xffffffffu, wreg, j & 31) : s_w[j];
        const float2 v0 = __ldcs(&xA[f0]);
        const float2 v1 = __ldcs(&xA[f1]);
        a0.x = fmaf(wA, v0.x, a0.x); a0.y = fmaf(wA, v0.y, a0.y);
        a1.x = fmaf(wA, v1.x, a1.x); a1.y = fmaf(wA, v1.y, a1.y);
        if (has2) {
            const float2 v2 = __ldcs(&xA[f2]);
            a2.x = fmaf(wA, v2.x, a2.x); a2.y = fmaf(wA, v2.y, a2.y);
        }
    }

    uint32_t* __restrict__ outp = g_att_hl + (size_t)b * KPAD;
    store_hl(outp, f0, a0);
    store_hl(outp, f1, a1);
    if (has2) store_hl(outp, f2, a2);
}

// ---------------------------------------------------------------------------
// K2: logits = att @ rel^T + bias via mma.sync m16n8k16 bf16 (HMMA),
// 2-split 3-term: D += Ah*Bh + Ah*Bl + Al*Bh, fp32 accumulate.
// 256 threads: warp w -> m16 group (w&3), n32 group (w>>2). BM=64, N=64.
// Fragments loaded straight from interleaved (hi,lo) global arrays: LDG.64
// yields {hi_pair, lo_pair} = two fragment registers, zero conversion.
// ---------------------------------------------------------------------------
#define MMA16816(c0, c1, c2, c3, a0, a1, a2, a3, b0, b1) \
    asm volatile("mma.sync.aligned.m16n8k16.row.col.f32.bf16.bf16.f32 " \
        "{%0,%1,%2,%3}, {%4,%5,%6,%7}, {%8,%9}, {%0,%1,%2,%3};" \
        : "+f"(c0), "+f"(c1), "+f"(c2), "+f"(c3) \
        : "r"(a0), "r"(a1), "r"(a2), "r"(a3), "r"(b0), "r"(b1))

__global__ __launch_bounds__(256) void proj_hmma_kernel(
    const float* __restrict__ bias,
    float* __restrict__ out)
{
    const int tid  = threadIdx.x;
    const int wid  = tid >> 5;      // 0..7
    const int lane = tid & 31;
    const int gid  = lane >> 2;     // 0..7
    const int tig  = lane & 3;      // 0..3
    const int mg   = wid & 3;       // m16 group
    const int ng   = wid >> 2;      // 0..1 (n32 group)

    const int m0 = blockIdx.x * 64;
    const int r0 = m0 + mg * 16 + gid;
    const int r1 = r0 + 8;
    const int r0c = (r0 < NUM_BAGS) ? r0 : (NUM_BAGS - 1);
    const int r1c = (r1 < NUM_BAGS) ? r1 : (NUM_BAGS - 1);

    const uint32_t* __restrict__ A0p = g_att_hl + (size_t)r0c * KPAD;
    const uint32_t* __restrict__ A1p = g_att_hl + (size_t)r1c * KPAD;

    const int nb0 = ng * 4;
    const uint32_t* __restrict__ B0p = g_rel_hl + (size_t)((nb0 + 0) * 8 + gid) * KPAD;
    const uint32_t* __restrict__ B1p = g_rel_hl + (size_t)((nb0 + 1) * 8 + gid) * KPAD;
    const uint32_t* __restrict__ B2p = g_rel_hl + (size_t)((nb0 + 2) * 8 + gid) * KPAD;
    const uint32_t* __restrict__ B3p = g_rel_hl + (size_t)((nb0 + 3) * 8 + gid) * KPAD;

    float c[4][4];
    #pragma unroll
    for (int i = 0; i < 4; i++)
        #pragma unroll
        for (int q = 0; q < 4; q++) c[i][q] = 0.0f;

    #pragma unroll 2
    for (int kt = 0; kt < 44; kt++) {
        const int cp = (kt << 3) + tig;          // bf16x2 pair index (k = 2*cp)
        // A fragments: {hi,lo} in one LDG.64 each
        const uint2 A0 = *(const uint2*)(A0p + 2 * cp);          // row gid,   k..k+1
        const uint2 A1 = *(const uint2*)(A1p + 2 * cp);          // row gid+8, k..k+1
        const uint2 A2 = *(const uint2*)(A0p + 2 * (cp + 4));    // row gid,   k+8..k+9
        const uint2 A3 = *(const uint2*)(A1p + 2 * (cp + 4));    // row gid+8, k+8..k+9

        const uint2 Bb0 = *(const uint2*)(B0p + 2 * cp);
        const uint2 Bb0h = *(const uint2*)(B0p + 2 * (cp + 4));
        MMA16816(c[0][0], c[0][1], c[0][2], c[0][3], A0.x, A1.x, A2.x, A3.x, Bb0.x, Bb0h.x);
        MMA16816(c[0][0], c[0][1], c[0][2], c[0][3], A0.x, A1.x, A2.x, A3.x, Bb0.y, Bb0h.y);
        MMA16816(c[0][0], c[0][1], c[0][2], c[0][3], A0.y, A1.y, A2.y, A3.y, Bb0.x, Bb0h.x);

        const uint2 Bb1 = *(const uint2*)(B1p + 2 * cp);
        const uint2 Bb1h = *(const uint2*)(B1p + 2 * (cp + 4));
        MMA16816(c[1][0], c[1][1], c[1][2], c[1][3], A0.x, A1.x, A2.x, A3.x, Bb1.x, Bb1h.x);
        MMA16816(c[1][0], c[1][1], c[1][2], c[1][3], A0.x, A1.x, A2.x, A3.x, Bb1.y, Bb1h.y);
        MMA16816(c[1][0], c[1][1], c[1][2], c[1][3], A0.y, A1.y, A2.y, A3.y, Bb1.x, Bb1h.x);

        const uint2 Bb2 = *(const uint2*)(B2p + 2 * cp);
        const uint2 Bb2h = *(const uint2*)(B2p + 2 * (cp + 4));
        MMA16816(c[2][0], c[2][1], c[2][2], c[2][3], A0.x, A1.x, A2.x, A3.x, Bb2.x, Bb2h.x);
        MMA16816(c[2][0], c[2][1], c[2][2], c[2][3], A0.x, A1.x, A2.x, A3.x, Bb2.y, Bb2h.y);
        MMA16816(c[2][0], c[2][1], c[2][2], c[2][3], A0.y, A1.y, A2.y, A3.y, Bb2.x, Bb2h.x);

        const uint2 Bb3 = *(const uint2*)(B3p + 2 * cp);
        const uint2 Bb3h = *(const uint2*)(B3p + 2 * (cp + 4));
        MMA16816(c[3][0], c[3][1], c[3][2], c[3][3], A0.x, A1.x, A2.x, A3.x, Bb3.x, Bb3h.x);
        MMA16816(c[3][0], c[3][1], c[3][2], c[3][3], A0.x, A1.x, A2.x, A3.x, Bb3.y, Bb3h.y);
        MMA16816(c[3][0], c[3][1], c[3][2], c[3][3], A0.y, A1.y, A2.y, A3.y, Bb3.x, Bb3h.x);
    }

    // epilogue: c[nb][0]=(r0, n), [1]=(r0, n+1), [2]=(r1, n), [3]=(r1, n+1)
    #pragma unroll
    for (int nb = 0; nb < 4; nb++) {
        const int n = (nb0 + nb) * 8 + 2 * tig;
        const bool n0ok = (n < RR);
        const bool n1ok = (n + 1 < RR);
        const float bv0 = n0ok ? bias[n] : 0.0f;
        const float bv1 = n1ok ? bias[n + 1] : 0.0f;
        if (r0 < NUM_BAGS) {
            if (n0ok) out[(size_t)r0 * RR + n]     = c[nb][0] + bv0;
            if (n1ok) out[(size_t)r0 * RR + n + 1] = c[nb][1] + bv1;
        }
        if (r1 < NUM_BAGS) {
            if (n0ok) out[(size_t)r1 * RR + n]     = c[nb][2] + bv0;
            if (n1ok) out[(size_t)r1 * RR + n + 1] = c[nb][3] + bv1;
        }
    }
}

extern "C" void kernel_launch(void* const* d_in, const int* in_sizes, int n_in,
                              void* d_out, int out_size)
{
    const float* repre  = (const float*)d_in[0];
    const float* relmat = (const float*)d_in[1];
    const float* bias   = (const float*)d_in[2];
    const void*  scope  = d_in[3];
    const void*  labels = d_in[4];
    float* out = (float*)d_out;

    rel_prep_kernel<<<64, 128>>>(relmat);
    bag_attn_kernel<<<NUM_BAGS, 128>>>(repre, relmat, scope, labels);
    proj_hmma_kernel<<<(NUM_BAGS + 63) / 64, 256>>>(bias, out);
}

// round 13
// speedup vs baseline: 1.2036x; 1.0302x over previous
#include <cuda_runtime.h>
#include <cuda_bf16.h>
#include <math.h>
#include <cstdint>

#define NN 200000
#define NUM_BAGS 25000
#define DD 690
#define D2 345          // DD/2 float2s
#define RR 53
#define MAX_BAG 256
#define KPAD 704        // DD padded to 44*16
#define PAIRS 352       // KPAD/2 bf16x2 pairs per row
#define NTILES 7        // ceil(53/8) n8-tiles

// Interleaved (hi,lo) bf16x2 storage: row-major, u32 col 2c = hi pair (d=2c,2c+1),
// u32 col 2c+1 = lo pair. Cols for d>=690 stay zero (static zero-init, never written).
__device__ uint32_t g_att_hl[(size_t)NUM_BAGS * KPAD];   // 70.4 MB
// B in fragment-major layout: [ntile][kt][lane][4] = {bh(p), bl(p), bh(p+4), bl(p+4)}
__device__ uint32_t g_rel_fr[(size_t)NTILES * 44 * 32 * 4];

__device__ __forceinline__ int sniff_is64(const void* scope)
{
    return (((const int*)scope)[1] == 0) ? 1 : 0;
}

__device__ __forceinline__ int load_idx(const void* p, int i, int is64)
{
    return is64 ? (int)((const long long*)p)[i] : ((const int*)p)[i];
}

__device__ __forceinline__ uint32_t smem_u32(const void* p)
{
    uint32_t addr;
    asm("{ .reg .u64 tmp; cvta.to.shared.u64 tmp, %1; cvt.u32.u64 %0, tmp; }"
        : "=r"(addr) : "l"(p));
    return addr;
}

__device__ __forceinline__ void store_hl(uint32_t* __restrict__ row, int f, float2 v)
{
    __nv_bfloat16 hx = __float2bfloat16(v.x);
    __nv_bfloat16 hy = __float2bfloat16(v.y);
    __nv_bfloat16 lx = __float2bfloat16(v.x - __bfloat162float(hx));
    __nv_bfloat16 ly = __float2bfloat16(v.y - __bfloat162float(hy));
    __nv_bfloat162 hh; hh.x = hx; hh.y = hy;
    __nv_bfloat162 ll; ll.x = lx; ll.y = ly;
    row[2 * f]     = *reinterpret_cast<uint32_t*>(&hh);
    row[2 * f + 1] = *reinterpret_cast<uint32_t*>(&ll);
}

__device__ __forceinline__ uint32_t bf16x2_split_hi(float v0, float v1, uint32_t* lo)
{
    __nv_bfloat16 h0 = __float2bfloat16(v0);
    __nv_bfloat16 h1 = __float2bfloat16(v1);
    __nv_bfloat16 l0 = __float2bfloat16(v0 - __bfloat162float(h0));
    __nv_bfloat16 l1 = __float2bfloat16(v1 - __bfloat162float(h1));
    __nv_bfloat162 hh; hh.x = h0; hh.y = h1;
    __nv_bfloat162 ll; ll.x = l0; ll.y = l1;
    *lo = *reinterpret_cast<uint32_t*>(&ll);
    return *reinterpret_cast<uint32_t*>(&hh);
}

// ---------------------------------------------------------------------------
// rel prep: build fragment-major B. Entry e = (nt, kt, lane).
// value col n = nt*8 + gid, pairs p1 = 8kt+tig, p2 = p1+4.
// ---------------------------------------------------------------------------
__global__ void rel_prep_kernel(const float* __restrict__ relp)
{
    const int e = blockIdx.x * blockDim.x + threadIdx.x;
    if (e >= NTILES * 44 * 32) return;
    const int nt   = e / (44 * 32);
    const int rem  = e % (44 * 32);
    const int kt   = rem >> 5;
    const int lane = rem & 31;
    const int gid  = lane >> 2;
    const int tig  = lane & 3;
    const int n    = nt * 8 + gid;
    const int p1   = 8 * kt + tig;
    const int p2   = p1 + 4;

    float a0 = 0.0f, a1 = 0.0f, b0 = 0.0f, b1 = 0.0f;
    if (n < RR) {
        if (2 * p1 < DD)     a0 = relp[(size_t)n * DD + 2 * p1];
        if (2 * p1 + 1 < DD) a1 = relp[(size_t)n * DD + 2 * p1 + 1];
        if (2 * p2 < DD)     b0 = relp[(size_t)n * DD + 2 * p2];
        if (2 * p2 + 1 < DD) b1 = relp[(size_t)n * DD + 2 * p2 + 1];
    }
    uint32_t lo1, lo2;
    const uint32_t hi1 = bf16x2_split_hi(a0, a1, &lo1);
    const uint32_t hi2 = bf16x2_split_hi(b0, b1, &lo2);
    uint4 v; v.x = hi1; v.y = lo1; v.z = hi2; v.w = lo2;
    *reinterpret_cast<uint4*>(g_rel_fr + (size_t)e * 4) = v;
}

// ---------------------------------------------------------------------------
// K1 (exact R12, measured ~137us): block per bag, 128 threads.
// ---------------------------------------------------------------------------
__global__ __launch_bounds__(128, 10) void bag_attn_kernel(
    const float* __restrict__ repre,
    const float* __restrict__ rel,
    const void*  __restrict__ scope,
    const void*  __restrict__ labels)
{
    __shared__ float s_rl[MAX_BAG];
    __shared__ float s_w[MAX_BAG];

    const int tid  = threadIdx.x;
    const int wid  = tid >> 5;
    const int lane = tid & 31;
    const int is64 = sniff_is64(scope);

    const int b = blockIdx.x;
    int start = load_idx(scope, 2 * b, is64);
    int end   = load_idx(scope, 2 * b + 1, is64);
    if (start < 0) start = 0;
    if (start > NN) start = NN;
    if (end < start) end = start;
    if (end > NN) end = NN;
    int nb = end - start;
    if (nb > MAX_BAG) nb = MAX_BAG;

    int mylab = 0;
    {
        const int j = wid + 4 * lane;
        if (j < nb) {
            int lab = load_idx(labels, start + j, is64);
            if (lab < 0) lab = 0;
            if (lab >= RR) lab = RR - 1;
            mylab = lab;
        }
    }

    for (int k = 0; ; k++) {
        const int j = wid + 4 * k;
        if (j >= nb) break;
        int lab;
        if (k < 32) {
            lab = __shfl_sync(0xffffffffu, mylab, k);
        } else {
            lab = load_idx(labels, start + j, is64);
            if (lab < 0) lab = 0;
            if (lab >= RR) lab = RR - 1;
        }
        const float2* __restrict__ xr2 = (const float2*)(repre + (size_t)(start + j) * DD);
        const float2* __restrict__ rr2 = (const float2*)(rel + (size_t)lab * DD);
        float acc = 0.0f;
        #pragma unroll
        for (int it = 0; it < 10; it++) {
            const int d = lane + 32 * it;
            const float2 x = xr2[d];
            const float2 r = rr2[d];
            acc = fmaf(x.x, r.x, acc);
            acc = fmaf(x.y, r.y, acc);
        }
        {
            const int d = 320 + lane;
            if (d < D2) {
                const float2 x = xr2[d];
                const float2 r = rr2[d];
                acc = fmaf(x.x, r.x, acc);
                acc = fmaf(x.y, r.y, acc);
            }
        }
        #pragma unroll
        for (int o = 16; o > 0; o >>= 1)
            acc += __shfl_xor_sync(0xffffffffu, acc, o);
        if (lane == 0) s_rl[j] = acc;
    }
    __syncthreads();

    const bool fast = (nb <= 32);
    float wreg = 0.0f;
    if (fast) {
        float t = (lane < nb) ? s_rl[lane] : -INFINITY;
        float m = t;
        #pragma unroll
        for (int o = 16; o > 0; o >>= 1)
            m = fmaxf(m, __shfl_xor_sync(0xffffffffu, m, o));
        float e = (lane < nb) ? expf(t - m) : 0.0f;
        float s = e;
        #pragma unroll
        for (int o = 16; o > 0; o >>= 1)
            s += __shfl_xor_sync(0xffffffffu, s, o);
        wreg = e / s;
    } else {
        if (wid == 0) {
            float m = -INFINITY;
            for (int j = lane; j < nb; j += 32) m = fmaxf(m, s_rl[j]);
            #pragma unroll
            for (int o = 16; o > 0; o >>= 1)
                m = fmaxf(m, __shfl_xor_sync(0xffffffffu, m, o));
            float s = 0.0f;
            for (int j = lane; j < nb; j += 32) {
                float e = expf(s_rl[j] - m);
                s_w[j] = e;
                s += e;
            }
            #pragma unroll
            for (int o = 16; o > 0; o >>= 1)
                s += __shfl_xor_sync(0xffffffffu, s, o);
            float inv = 1.0f / s;
            for (int j = lane; j < nb; j += 32) s_w[j] *= inv;
        }
        __syncthreads();
    }

    const int f0 = tid;
    const int f1 = tid + 128;
    const int f2 = tid + 256;
    const bool has2 = (f2 < D2);
    float2 a0 = make_float2(0.0f, 0.0f);
    float2 a1 = make_float2(0.0f, 0.0f);
    float2 a2 = make_float2(0.0f, 0.0f);

    int j = 0;
    for (; j + 3 < nb; j += 4) {
        const float2* __restrict__ x0 = (const float2*)(repre + (size_t)(start + j    ) * DD);
        const float2* __restrict__ x1 = (const float2*)(repre + (size_t)(start + j + 1) * DD);
        const float2* __restrict__ x2 = (const float2*)(repre + (size_t)(start + j + 2) * DD);
        const float2* __restrict__ x3 = (const float2*)(repre + (size_t)(start + j + 3) * DD);
        float w0, w1, w2, w3;
        if (fast) {
            w0 = __shfl_sync(0xffffffffu, wreg, j & 31);
            w1 = __shfl_sync(0xffffffffu, wreg, (j + 1) & 31);
            w2 = __shfl_sync(0xffffffffu, wreg, (j + 2) & 31);
            w3 = __shfl_sync(0xffffffffu, wreg, (j + 3) & 31);
        } else {
            w0 = s_w[j]; w1 = s_w[j + 1]; w2 = s_w[j + 2]; w3 = s_w[j + 3];
        }
        const float2 p00 = __ldcs(&x0[f0]), p10 = __ldcs(&x1[f0]),
                     p20 = __ldcs(&x2[f0]), p30 = __ldcs(&x3[f0]);
        const float2 p01 = __ldcs(&x0[f1]), p11 = __ldcs(&x1[f1]),
                     p21 = __ldcs(&x2[f1]), p31 = __ldcs(&x3[f1]);
        float2 p02, p12, p22, p32;
        if (has2) { p02 = __ldcs(&x0[f2]); p12 = __ldcs(&x1[f2]);
                    p22 = __ldcs(&x2[f2]); p32 = __ldcs(&x3[f2]); }
        a0.x = fmaf(w0, p00.x, a0.x); a0.y = fmaf(w0, p00.y, a0.y);
        a0.x = fmaf(w1, p10.x, a0.x); a0.y = fmaf(w1, p10.y, a0.y);
        a0.x = fmaf(w2, p20.x, a0.x); a0.y = fmaf(w2, p20.y, a0.y);
        a0.x = fmaf(w3, p30.x, a0.x); a0.y = fmaf(w3, p30.y, a0.y);
        a1.x = fmaf(w0, p01.x, a1.x); a1.y = fmaf(w0, p01.y, a1.y);
        a1.x = fmaf(w1, p11.x, a1.x); a1.y = fmaf(w1, p11.y, a1.y);
        a1.x = fmaf(w2, p21.x, a1.x); a1.y = fmaf(w2, p21.y, a1.y);
        a1.x = fmaf(w3, p31.x, a1.x); a1.y = fmaf(w3, p31.y, a1.y);
        if (has2) {
            a2.x = fmaf(w0, p02.x, a2.x); a2.y = fmaf(w0, p02.y, a2.y);
            a2.x = fmaf(w1, p12.x, a2.x); a2.y = fmaf(w1, p12.y, a2.y);
            a2.x = fmaf(w2, p22.x, a2.x); a2.y = fmaf(w2, p22.y, a2.y);
            a2.x = fmaf(w3, p32.x, a2.x); a2.y = fmaf(w3, p32.y, a2.y);
        }
    }
    for (; j < nb; j++) {
        const float2* __restrict__ xA = (const float2*)(repre + (size_t)(start + j) * DD);
        const float wA = fast ? __shfl_sync(0xffffffffu, wreg, j & 31) : s_w[j];
        const float2 v0 = __ldcs(&xA[f0]);
        const float2 v1 = __ldcs(&xA[f1]);
        a0.x = fmaf(wA, v0.x, a0.x); a0.y = fmaf(wA, v0.y, a0.y);
        a1.x = fmaf(wA, v1.x, a1.x); a1.y = fmaf(wA, v1.y, a1.y);
        if (has2) {
            const float2 v2 = __ldcs(&xA[f2]);
            a2.x = fmaf(wA, v2.x, a2.x); a2.y = fmaf(wA, v2.y, a2.y);
        }
    }

    uint32_t* __restrict__ outp = g_att_hl + (size_t)b * KPAD;
    store_hl(outp, f0, a0);
    store_hl(outp, f1, a1);
    if (has2) store_hl(outp, f2, a2);
}

// ---------------------------------------------------------------------------
// K2: HMMA with smem-staged A (ldmatrix) + fragment-major B (coalesced LDG).
// BM=64 (4 m16 blocks), 8 warps: mg = wid&3, ng = wid>>1... ng = wid>>2.
// Per kt: stage A slab (64 rows x 8 pairs, hi/lo de-interleaved, row stride
// 48B -> LDSM conflict-free & 16B-aligned), 2x ldmatrix.x4 per warp,
// 3-4 uint4 B loads per warp, 9-12 HMMAs.
// ---------------------------------------------------------------------------
#define MMA16816(c0, c1, c2, c3, a0, a1, a2, a3, b0, b1) \
    asm volatile("mma.sync.aligned.m16n8k16.row.col.f32.bf16.bf16.f32 " \
        "{%0,%1,%2,%3}, {%4,%5,%6,%7}, {%8,%9}, {%0,%1,%2,%3};" \
        : "+f"(c0), "+f"(c1), "+f"(c2), "+f"(c3) \
        : "r"(a0), "r"(a1), "r"(a2), "r"(a3), "r"(b0), "r"(b1))

#define LDSM_X4(r0, r1, r2, r3, addr) \
    asm volatile("ldmatrix.sync.aligned.m8n8.x4.shared.b16 {%0,%1,%2,%3}, [%4];" \
        : "=r"(r0), "=r"(r1), "=r"(r2), "=r"(r3) : "r"(addr))

#define ROWSTRIDE 12    // u32 per smem tile row (48B: LDSM-conflict-free, 16B-aligned)

__global__ __launch_bounds__(256) void proj_hmma_kernel(
    const float* __restrict__ bias,
    float* __restrict__ out)
{
    __shared__ __align__(16) uint32_t sAhi[2][64 * ROWSTRIDE];
    __shared__ __align__(16) uint32_t sAlo[2][64 * ROWSTRIDE];

    const int tid  = threadIdx.x;
    const int wid  = tid >> 5;      // 0..7
    const int lane = tid & 31;
    const int gid  = lane >> 2;
    const int tig  = lane & 3;
    const int mg   = wid & 3;       // m16 block within CTA
    const int ng   = wid >> 2;      // 0..1: n-tiles 4ng..4ng+3

    const int m0 = blockIdx.x * 64;

    // staging coords: 4 threads per row, each loads 1 uint4 (2 pairs hi/lo)
    const int srow = tid >> 2;      // 0..63
    const int sseg = tid & 3;       // 0..3 -> local pairs 2seg, 2seg+1
    const bool sok = (m0 + srow) < NUM_BAGS;
    const uint32_t* __restrict__ aptr = g_att_hl + (size_t)(m0 + srow) * KPAD;
    const int sidx = srow * ROWSTRIDE + 2 * sseg;

    // LDSM per-lane address offset within a tile:
    //  lanes 0-15 -> mat0/1 rows 0..15 col 0 ; lanes 16-31 -> mat2/3 rows 0..15 col 4
    const int arow  = 16 * mg + (lane & 15);
    const int acol  = (lane < 16) ? 0 : 4;
    const uint32_t a_off = (uint32_t)(arow * ROWSTRIDE + acol) * 4u;
    const uint32_t ahi_base = smem_u32(&sAhi[0][0]);
    const uint32_t alo_base = smem_u32(&sAlo[0][0]);
    const uint32_t bufstride = 64 * ROWSTRIDE * 4u;   // bytes per buffer

    float c[4][4];
    #pragma unroll
    for (int i = 0; i < 4; i++)
        #pragma unroll
        for (int q = 0; q < 4; q++) c[i][q] = 0.0f;

    // prologue: stage kt=0
    {
        uint4 av = make_uint4(0, 0, 0, 0);
        if (sok) av = *(const uint4*)(aptr + 4 * sseg);
        *(uint2*)&sAhi[0][sidx] = make_uint2(av.x, av.z);
        *(uint2*)&sAlo[0][sidx] = make_uint2(av.y, av.w);
    }
    __syncthreads();

    int buf = 0;
    for (int kt = 0; kt < 44; kt++) {
        const bool more = (kt + 1 < 44);
        uint4 av = make_uint4(0, 0, 0, 0);
        if (more && sok) av = *(const uint4*)(aptr + 16 * (kt + 1) + 4 * sseg);

        // A fragments via ldmatrix
        uint32_t ah0, ah1, ah2, ah3, al0, al1, al2, al3;
        LDSM_X4(ah0, ah1, ah2, ah3, ahi_base + buf * bufstride + a_off);
        LDSM_X4(al0, al1, al2, al3, alo_base + buf * bufstride + a_off);

        // B fragments: coalesced uint4 per n-tile (L1/L2-hot)
        #pragma unroll
        for (int jj = 0; jj < 4; jj++) {
            const int t = 4 * ng + jj;
            if (t < NTILES) {
                const uint4 bv = *(const uint4*)(g_rel_fr +
                    (size_t)((t * 44 + kt) * 32 + lane) * 4);
                MMA16816(c[jj][0], c[jj][1], c[jj][2], c[jj][3],
                         ah0, ah1, ah2, ah3, bv.x, bv.z);
                MMA16816(c[jj][0], c[jj][1], c[jj][2], c[jj][3],
                         ah0, ah1, ah2, ah3, bv.y, bv.w);
                MMA16816(c[jj][0], c[jj][1], c[jj][2], c[jj][3],
                         al0, al1, al2, al3, bv.x, bv.z);
            }
        }

        if (more) {
            const int nb = buf ^ 1;
            *(uint2*)&sAhi[nb][sidx] = make_uint2(av.x, av.z);
            *(uint2*)&sAlo[nb][sidx] = make_uint2(av.y, av.w);
        }
        __syncthreads();
        buf ^= 1;
    }

    // epilogue: c[j][0]=(r0,n), [1]=(r0,n+1), [2]=(r1,n), [3]=(r1,n+1)
    const int r0 = m0 + mg * 16 + gid;
    const int r1 = r0 + 8;
    #pragma unroll
    for (int jj = 0; jj < 4; jj++) {
        const int t = 4 * ng + jj;
        if (t >= NTILES) continue;
        const int n = t * 8 + 2 * tig;
        const bool n0ok = (n < RR);
        const bool n1ok = (n + 1 < RR);
        const float bv0 = n0ok ? bias[n] : 0.0f;
        const float bv1 = n1ok ? bias[n + 1] : 0.0f;
        if (r0 < NUM_BAGS) {
            if (n0ok) out[(size_t)r0 * RR + n]     = c[jj][0] + bv0;
            if (n1ok) out[(size_t)r0 * RR + n + 1] = c[jj][1] + bv1;
        }
        if (r1 < NUM_BAGS) {
            if (n0ok) out[(size_t)r1 * RR + n]     = c[jj][2] + bv0;
            if (n1ok) out[(size_t)r1 * RR + n + 1] = c[jj][3] + bv1;
        }
    }
}

extern "C" void kernel_launch(void* const* d_in, const int* in_sizes, int n_in,
                              void* d_out, int out_size)
{
    const float* repre  = (const float*)d_in[0];
    const float* relmat = (const float*)d_in[1];
    const float* bias   = (const float*)d_in[2];
    const void*  scope  = d_in[3];
    const void*  labels = d_in[4];
    float* out = (float*)d_out;

    rel_prep_kernel<<<(NTILES * 44 * 32 + 127) / 128, 128>>>(relmat);
    bag_attn_kernel<<<NUM_BAGS, 128>>>(repre, relmat, scope, labels);
    proj_hmma_kernel<<<(NUM_BAGS + 63) / 64, 256>>>(bias, out);
}